// round 6
// baseline (speedup 1.0000x reference)
#include <cuda_runtime.h>

#define NQ 6
#define DIM 64
#define NL 8
#define BATCH 262144
#define NCLS 4

// Precomputed circuit operator (transposed) and folded sign/fc matrix.
// g_Wt[j*64 + i] = W[i][j]  (complex, float2)
__device__ float2 g_Wt[DIM * DIM];
__device__ float4 g_G[DIM];   // G[i][k] = sum_q sign(i,q) * fc_w[k][q]

__device__ __forceinline__ float2 cmul(float2 a, float2 b) {
    return make_float2(a.x * b.x - a.y * b.y, a.x * b.y + a.y * b.x);
}

// ---------------------------------------------------------------------------
// Kernel 1: build the full 64x64 circuit unitary from weights (one block).
// ---------------------------------------------------------------------------
__global__ void build_W_kernel(const float* __restrict__ weights,
                               const float* __restrict__ fc_w) {
    __shared__ float2 M[DIM * DIM];
    const int tid = threadIdx.x;
    const int nthr = blockDim.x;

    for (int idx = tid; idx < DIM * DIM; idx += nthr) {
        int i = idx >> 6, j = idx & 63;
        M[idx] = make_float2(i == j ? 1.0f : 0.0f, 0.0f);
    }
    __syncthreads();

    for (int l = 0; l < NL; l++) {
        // --- rotation layer ---
        for (int q = 0; q < NQ; q++) {
            const int b = 5 - q;
            const int mask = 1 << b;
            const float phi = weights[(l * NQ + q) * 3 + 0];
            const float th  = weights[(l * NQ + q) * 3 + 1];
            const float om  = weights[(l * NQ + q) * 3 + 2];
            const float ch = cosf(0.5f * th), sh = sinf(0.5f * th);
            const float a  = 0.5f * (phi + om), d = 0.5f * (phi - om);
            const float ca = cosf(a), sa = sinf(a);
            const float cd = cosf(d), sd = sinf(d);
            const float2 u00 = make_float2( ch * ca, -ch * sa);
            const float2 u01 = make_float2(-sh * cd, -sh * sd);
            const float2 u10 = make_float2( sh * cd, -sh * sd);
            const float2 u11 = make_float2( ch * ca,  ch * sa);

            for (int idx = tid; idx < 32 * DIM; idx += nthr) {
                const int j  = idx & 63;
                const int pr = idx >> 6;                       // 5-bit
                const int r0 = ((pr >> b) << (b + 1)) | (pr & (mask - 1));
                const int r1 = r0 | mask;
                const float2 A = M[r0 * 64 + j];
                const float2 B = M[r1 * 64 + j];
                float2 nA = cmul(u00, A);
                float2 nB = cmul(u10, A);
                float2 tA = cmul(u01, B);
                float2 tB = cmul(u11, B);
                M[r0 * 64 + j] = make_float2(nA.x + tA.x, nA.y + tA.y);
                M[r1 * 64 + j] = make_float2(nB.x + tB.x, nB.y + tB.y);
            }
            __syncthreads();
        }
        // --- CNOT ring, range r ---
        const int r = (l % (NQ - 1)) + 1;
        for (int q = 0; q < NQ; q++) {
            const int t  = (q + r) % NQ;
            const int bc = 5 - q;
            const int bt = 5 - t;
            const int lo = bc < bt ? bc : bt;
            const int hi = bc < bt ? bt : bc;
            for (int idx = tid; idx < 16 * DIM; idx += nthr) {
                const int j  = idx & 63;
                const int pr = idx >> 6;                       // 4-bit
                int x1   = ((pr >> lo) << (lo + 1)) | (pr & ((1 << lo) - 1));
                int base = ((x1 >> hi) << (hi + 1)) | (x1 & ((1 << hi) - 1));
                const int rA = base | (1 << bc);               // control=1, target=0
                const int rB = rA | (1 << bt);                 // control=1, target=1
                const float2 tmp = M[rA * 64 + j];
                M[rA * 64 + j] = M[rB * 64 + j];
                M[rB * 64 + j] = tmp;
            }
            __syncthreads();
        }
    }

    // Write transposed operator: g_Wt[j*64+i] = M[i][j]
    for (int idx = tid; idx < DIM * DIM; idx += nthr) {
        const int j = idx >> 6, i = idx & 63;
        g_Wt[idx] = M[i * 64 + j];
    }
    // Folded sign/fc matrix G
    for (int i = tid; i < DIM; i += nthr) {
        float4 g = make_float4(0.f, 0.f, 0.f, 0.f);
        for (int q = 0; q < NQ; q++) {
            const float sgn = ((i >> (5 - q)) & 1) ? -1.0f : 1.0f;
            g.x += sgn * fc_w[0 * NQ + q];
            g.y += sgn * fc_w[1 * NQ + q];
            g.z += sgn * fc_w[2 * NQ + q];
            g.w += sgn * fc_w[3 * NQ + q];
        }
        g_G[i] = g;
    }
}

// ---------------------------------------------------------------------------
// Kernel 2: batched complex matvec + |.|^2 + folded linear head.
// One warp handles 8 samples per chunk; lane t owns output rows 2t, 2t+1.
// ---------------------------------------------------------------------------
#define BLK 256
#define WPB (BLK / 32)
#define SPW 8

__global__ __launch_bounds__(BLK) void qnn_main_kernel(
    const float* __restrict__ x,
    const float* __restrict__ fc_b,
    float* __restrict__ out) {
    __shared__ float4 Wsh[DIM * DIM / 2];        // 32 KB, Wt as float4 (2 complex)
    __shared__ float  Xsh[WPB][SPW * DIM];       // 16 KB, per-warp [s][j]

    const int tid  = threadIdx.x;
    const int warp = tid >> 5;
    const int lane = tid & 31;

    // Stage W into shared (float4 = {re0,im0,re1,im1} of rows 2t,2t+1 at column j)
    const float4* Wg = (const float4*)g_Wt;
#pragma unroll
    for (int idx = tid; idx < DIM * DIM / 2; idx += BLK) Wsh[idx] = Wg[idx];
    __syncthreads();

    const float4 Ga = g_G[2 * lane];
    const float4 Gb = g_G[2 * lane + 1];
    const float4 bb = *(const float4*)fc_b;

    float* Xw = Xsh[warp];

    const int gwarp   = blockIdx.x * WPB + warp;
    const int nwarps  = gridDim.x * WPB;
    const int nchunks = BATCH / SPW;

    for (int chunk = gwarp; chunk < nchunks; chunk += nwarps) {
        const int b0 = chunk * SPW;

        // ---- load 8 samples, compute squared norms, stage into shared ----
        float n2[SPW];
        __syncwarp();
#pragma unroll
        for (int s = 0; s < SPW; s++) {
            float2 v = ((const float2*)(x + (size_t)(b0 + s) * DIM))[lane];
            float sq = fmaf(v.x, v.x, v.y * v.y);
#pragma unroll
            for (int off = 16; off > 0; off >>= 1)
                sq += __shfl_xor_sync(0xffffffffu, sq, off);
            n2[s] = sq;
            ((float2*)(Xw + s * DIM))[lane] = v;
        }
        __syncwarp();

        // ---- y = W x for 8 samples; lane owns rows 2t (r0,i0) and 2t+1 (r1,i1)
        float r0[SPW], i0[SPW], r1[SPW], i1[SPW];
#pragma unroll
        for (int s = 0; s < SPW; s++) { r0[s] = i0[s] = r1[s] = i1[s] = 0.0f; }

#pragma unroll 2
        for (int j4 = 0; j4 < DIM / 4; j4++) {
            const float4 w0 = Wsh[(j4 * 4 + 0) * 32 + lane];
            const float4 w1 = Wsh[(j4 * 4 + 1) * 32 + lane];
            const float4 w2 = Wsh[(j4 * 4 + 2) * 32 + lane];
            const float4 w3 = Wsh[(j4 * 4 + 3) * 32 + lane];
#pragma unroll
            for (int s = 0; s < SPW; s++) {
                const float4 xv = *(const float4*)(Xw + s * DIM + j4 * 4);
                r0[s] = fmaf(w0.x, xv.x, r0[s]);
                i0[s] = fmaf(w0.y, xv.x, i0[s]);
                r1[s] = fmaf(w0.z, xv.x, r1[s]);
                i1[s] = fmaf(w0.w, xv.x, i1[s]);

                r0[s] = fmaf(w1.x, xv.y, r0[s]);
                i0[s] = fmaf(w1.y, xv.y, i0[s]);
                r1[s] = fmaf(w1.z, xv.y, r1[s]);
                i1[s] = fmaf(w1.w, xv.y, i1[s]);

                r0[s] = fmaf(w2.x, xv.z, r0[s]);
                i0[s] = fmaf(w2.y, xv.z, i0[s]);
                r1[s] = fmaf(w2.z, xv.z, r1[s]);
                i1[s] = fmaf(w2.w, xv.z, i1[s]);

                r0[s] = fmaf(w3.x, xv.w, r0[s]);
                i0[s] = fmaf(w3.y, xv.w, i0[s]);
                r1[s] = fmaf(w3.z, xv.w, r1[s]);
                i1[s] = fmaf(w3.w, xv.w, i1[s]);
            }
        }

        // ---- epilogue: probs -> folded linear head -> warp reduce -> store
#pragma unroll
        for (int s = 0; s < SPW; s++) {
            const float inv = 1.0f / fmaxf(n2[s], 1e-24f);
            const float p0 = fmaf(r0[s], r0[s], i0[s] * i0[s]) * inv;
            const float p1 = fmaf(r1[s], r1[s], i1[s] * i1[s]) * inv;
            float4 part;
            part.x = fmaf(p0, Ga.x, p1 * Gb.x);
            part.y = fmaf(p0, Ga.y, p1 * Gb.y);
            part.z = fmaf(p0, Ga.z, p1 * Gb.z);
            part.w = fmaf(p0, Ga.w, p1 * Gb.w);
#pragma unroll
            for (int off = 16; off > 0; off >>= 1) {
                part.x += __shfl_xor_sync(0xffffffffu, part.x, off);
                part.y += __shfl_xor_sync(0xffffffffu, part.y, off);
                part.z += __shfl_xor_sync(0xffffffffu, part.z, off);
                part.w += __shfl_xor_sync(0xffffffffu, part.w, off);
            }
            if (lane == 0) {
                ((float4*)out)[b0 + s] = make_float4(part.x + bb.x, part.y + bb.y,
                                                     part.z + bb.z, part.w + bb.w);
            }
        }
    }
}

// ---------------------------------------------------------------------------
// Launch
// ---------------------------------------------------------------------------
extern "C" void kernel_launch(void* const* d_in, const int* in_sizes, int n_in,
                              void* d_out, int out_size) {
    const float* x       = (const float*)d_in[0];   // [262144, 64]
    const float* weights = (const float*)d_in[1];   // [8, 6, 3]
    const float* fc_w    = (const float*)d_in[2];   // [4, 6]
    const float* fc_b    = (const float*)d_in[3];   // [4]
    float* out           = (float*)d_out;           // [262144, 4]

    (void)in_sizes; (void)n_in; (void)out_size;

    build_W_kernel<<<1, 512>>>(weights, fc_w);
    qnn_main_kernel<<<1024, BLK>>>(x, fc_b, out);
}

// round 8
// speedup vs baseline: 1.0071x; 1.0071x over previous
#include <cuda_runtime.h>

#define NQ 6
#define DIM 64
#define NL 8
#define BATCH 262144
#define NCLS 4

typedef unsigned long long u64;

// Precomputed circuit operator (transposed) and folded sign/fc matrix.
// g_Wt[j*64 + i] = W[i][j]  (complex, float2 = {re, im})
__device__ float2 g_Wt[DIM * DIM];
__device__ float4 g_G[DIM];   // G[i][k] = sum_q sign(i,q) * fc_w[k][q]

__device__ __forceinline__ float2 cmul(float2 a, float2 b) {
    return make_float2(a.x * b.x - a.y * b.y, a.x * b.y + a.y * b.x);
}

__device__ __forceinline__ u64 fma2(u64 a, u64 b, u64 c) {
    u64 d;
    asm("fma.rn.f32x2 %0, %1, %2, %3;" : "=l"(d) : "l"(a), "l"(b), "l"(c));
    return d;
}

// ---------------------------------------------------------------------------
// Kernel 1: build the full 64x64 circuit unitary from weights (one block).
// ---------------------------------------------------------------------------
__global__ void build_W_kernel(const float* __restrict__ weights,
                               const float* __restrict__ fc_w) {
    __shared__ float2 M[DIM * DIM];
    const int tid = threadIdx.x;
    const int nthr = blockDim.x;

    for (int idx = tid; idx < DIM * DIM; idx += nthr) {
        int i = idx >> 6, j = idx & 63;
        M[idx] = make_float2(i == j ? 1.0f : 0.0f, 0.0f);
    }
    __syncthreads();

    for (int l = 0; l < NL; l++) {
        // --- rotation layer ---
        for (int q = 0; q < NQ; q++) {
            const int b = 5 - q;
            const int mask = 1 << b;
            const float phi = weights[(l * NQ + q) * 3 + 0];
            const float th  = weights[(l * NQ + q) * 3 + 1];
            const float om  = weights[(l * NQ + q) * 3 + 2];
            const float ch = cosf(0.5f * th), sh = sinf(0.5f * th);
            const float a  = 0.5f * (phi + om), d = 0.5f * (phi - om);
            const float ca = cosf(a), sa = sinf(a);
            const float cd = cosf(d), sd = sinf(d);
            const float2 u00 = make_float2( ch * ca, -ch * sa);
            const float2 u01 = make_float2(-sh * cd, -sh * sd);
            const float2 u10 = make_float2( sh * cd, -sh * sd);
            const float2 u11 = make_float2( ch * ca,  ch * sa);

            for (int idx = tid; idx < 32 * DIM; idx += nthr) {
                const int j  = idx & 63;
                const int pr = idx >> 6;                       // 5-bit
                const int r0 = ((pr >> b) << (b + 1)) | (pr & (mask - 1));
                const int r1 = r0 | mask;
                const float2 A = M[r0 * 64 + j];
                const float2 B = M[r1 * 64 + j];
                float2 nA = cmul(u00, A);
                float2 nB = cmul(u10, A);
                float2 tA = cmul(u01, B);
                float2 tB = cmul(u11, B);
                M[r0 * 64 + j] = make_float2(nA.x + tA.x, nA.y + tA.y);
                M[r1 * 64 + j] = make_float2(nB.x + tB.x, nB.y + tB.y);
            }
            __syncthreads();
        }
        // --- CNOT ring, range r ---
        const int r = (l % (NQ - 1)) + 1;
        for (int q = 0; q < NQ; q++) {
            const int t  = (q + r) % NQ;
            const int bc = 5 - q;
            const int bt = 5 - t;
            const int lo = bc < bt ? bc : bt;
            const int hi = bc < bt ? bt : bc;
            for (int idx = tid; idx < 16 * DIM; idx += nthr) {
                const int j  = idx & 63;
                const int pr = idx >> 6;                       // 4-bit
                int x1   = ((pr >> lo) << (lo + 1)) | (pr & ((1 << lo) - 1));
                int base = ((x1 >> hi) << (hi + 1)) | (x1 & ((1 << hi) - 1));
                const int rA = base | (1 << bc);               // control=1, target=0
                const int rB = rA | (1 << bt);                 // control=1, target=1
                const float2 tmp = M[rA * 64 + j];
                M[rA * 64 + j] = M[rB * 64 + j];
                M[rB * 64 + j] = tmp;
            }
            __syncthreads();
        }
    }

    // Write transposed operator: g_Wt[j*64+i] = M[i][j]
    for (int idx = tid; idx < DIM * DIM; idx += nthr) {
        const int j = idx >> 6, i = idx & 63;
        g_Wt[idx] = M[i * 64 + j];
    }
    // Folded sign/fc matrix G
    for (int i = tid; i < DIM; i += nthr) {
        float4 g = make_float4(0.f, 0.f, 0.f, 0.f);
        for (int q = 0; q < NQ; q++) {
            const float sgn = ((i >> (5 - q)) & 1) ? -1.0f : 1.0f;
            g.x += sgn * fc_w[0 * NQ + q];
            g.y += sgn * fc_w[1 * NQ + q];
            g.z += sgn * fc_w[2 * NQ + q];
            g.w += sgn * fc_w[3 * NQ + q];
        }
        g_G[i] = g;
    }
}

// ---------------------------------------------------------------------------
// Kernel 2: batched complex matvec via packed fma.rn.f32x2.
// One warp handles 8 samples per chunk; lane t owns output rows 2t, 2t+1.
// Accumulators are packed {re,im} pairs; x is stored duplicated {x,x} in
// shared so the packed multiplicand is a single broadcast LDS.
// ---------------------------------------------------------------------------
#define BLK 256
#define WPB (BLK / 32)
#define SPW 8
#define SAMP_STRIDE 528                         // bytes; 33 float4s (pad for epi)
#define WARP_SCRATCH 4352                       // >= 8*528, 128B aligned
#define SMEM_BYTES (DIM * DIM * 8 + WPB * WARP_SCRATCH)   // 32768 + 34816 = 67584

__global__ __launch_bounds__(BLK, 2) void qnn_main_kernel(
    const float* __restrict__ x,
    const float* __restrict__ fc_b,
    float* __restrict__ out) {
    extern __shared__ char smem[];
    // W region: [j][lane] as ulonglong2 = {{re0,im0},{re1,im1}} for rows 2lane,2lane+1
    ulonglong2* WshQ = (ulonglong2*)smem;
    char* scratch_all = smem + DIM * DIM * 8;

    const int tid  = threadIdx.x;
    const int warp = tid >> 5;
    const int lane = tid & 31;

    // Stage W into shared (already {re,im} adjacent = packed pairs)
    {
        const ulonglong2* Wg = (const ulonglong2*)g_Wt;
#pragma unroll
        for (int idx = tid; idx < DIM * DIM / 2; idx += BLK) WshQ[idx] = Wg[idx];
    }
    __syncthreads();

    const float4 Ga = g_G[2 * lane];
    const float4 Gb = g_G[2 * lane + 1];

    char* scr = scratch_all + warp * WARP_SCRATCH;
    // x staging view: per sample, 64 duplicated pairs (512B), stride 528B
    // stored as float4 {x0,x0,x1,x1} per 2 columns.

    const int gwarp   = blockIdx.x * WPB + warp;
    const int nwarps  = gridDim.x * WPB;
    const int nchunks = BATCH / SPW;

    for (int chunk = gwarp; chunk < nchunks; chunk += nwarps) {
        const int b0 = chunk * SPW;

        // ---- load 8 samples, squared norms, stage duplicated into shared ----
        float n2[SPW];
        __syncwarp();
#pragma unroll
        for (int s = 0; s < SPW; s++) {
            float2 v = ((const float2*)(x + (size_t)(b0 + s) * DIM))[lane];
            float sq = fmaf(v.x, v.x, v.y * v.y);
#pragma unroll
            for (int off = 16; off > 0; off >>= 1)
                sq += __shfl_xor_sync(0xffffffffu, sq, off);
            n2[s] = sq;
            ((float4*)(scr + s * SAMP_STRIDE))[lane] =
                make_float4(v.x, v.x, v.y, v.y);
        }
        __syncwarp();

        // ---- y = W x for 8 samples; packed complex accumulators ----
        u64 acc0[SPW], acc1[SPW];
#pragma unroll
        for (int s = 0; s < SPW; s++) { acc0[s] = 0ull; acc1[s] = 0ull; }

#pragma unroll 2
        for (int j4 = 0; j4 < DIM / 4; j4++) {
            const ulonglong2 wq0 = WshQ[(j4 * 4 + 0) * 32 + lane];
            const ulonglong2 wq1 = WshQ[(j4 * 4 + 1) * 32 + lane];
            const ulonglong2 wq2 = WshQ[(j4 * 4 + 2) * 32 + lane];
            const ulonglong2 wq3 = WshQ[(j4 * 4 + 3) * 32 + lane];
#pragma unroll
            for (int s = 0; s < SPW; s++) {
                const ulonglong2* xrow = (const ulonglong2*)(scr + s * SAMP_STRIDE);
                const ulonglong2 xa = xrow[j4 * 2 + 0];   // {{x0,x0},{x1,x1}}
                const ulonglong2 xb = xrow[j4 * 2 + 1];   // {{x2,x2},{x3,x3}}
                acc0[s] = fma2(wq0.x, xa.x, acc0[s]);
                acc1[s] = fma2(wq0.y, xa.x, acc1[s]);
                acc0[s] = fma2(wq1.x, xa.y, acc0[s]);
                acc1[s] = fma2(wq1.y, xa.y, acc1[s]);
                acc0[s] = fma2(wq2.x, xb.x, acc0[s]);
                acc1[s] = fma2(wq2.y, xb.x, acc1[s]);
                acc0[s] = fma2(wq3.x, xb.y, acc0[s]);
                acc1[s] = fma2(wq3.y, xb.y, acc1[s]);
            }
        }

        // ---- epilogue: probs -> folded head -> shared transpose reduce ----
        __syncwarp();
#pragma unroll
        for (int s = 0; s < SPW; s++) {
            const float inv = 1.0f / fmaxf(n2[s], 1e-24f);
            float r0, i0, r1, i1;
            asm("mov.b64 {%0, %1}, %2;" : "=f"(r0), "=f"(i0) : "l"(acc0[s]));
            asm("mov.b64 {%0, %1}, %2;" : "=f"(r1), "=f"(i1) : "l"(acc1[s]));
            const float p0 = fmaf(r0, r0, i0 * i0) * inv;
            const float p1 = fmaf(r1, r1, i1 * i1) * inv;
            float4 part;
            part.x = fmaf(p0, Ga.x, p1 * Gb.x);
            part.y = fmaf(p0, Ga.y, p1 * Gb.y);
            part.z = fmaf(p0, Ga.z, p1 * Gb.z);
            part.w = fmaf(p0, Ga.w, p1 * Gb.w);
            ((float4*)(scr + s * SAMP_STRIDE))[lane] = part;
        }
        __syncwarp();

        // lane -> (sample = lane>>2, class = lane&3); sum 32 partials.
        {
            const int s = lane >> 2;
            const int c = lane & 3;
            const float* base = (const float*)(scr + s * SAMP_STRIDE) + c;
            float a0 = 0.f, a1 = 0.f, a2 = 0.f, a3 = 0.f;
#pragma unroll
            for (int l = 0; l < 32; l += 4) {
                a0 += base[(l + 0) * 4];
                a1 += base[(l + 1) * 4];
                a2 += base[(l + 2) * 4];
                a3 += base[(l + 3) * 4];
            }
            const float res = (a0 + a1) + (a2 + a3) + fc_b[c];
            out[(size_t)b0 * NCLS + lane] = res;   // fully coalesced 128B
        }
    }
}

// ---------------------------------------------------------------------------
// Launch
// ---------------------------------------------------------------------------
extern "C" void kernel_launch(void* const* d_in, const int* in_sizes, int n_in,
                              void* d_out, int out_size) {
    const float* x       = (const float*)d_in[0];   // [262144, 64]
    const float* weights = (const float*)d_in[1];   // [8, 6, 3]
    const float* fc_w    = (const float*)d_in[2];   // [4, 6]
    const float* fc_b    = (const float*)d_in[3];   // [4]
    float* out           = (float*)d_out;           // [262144, 4]

    (void)in_sizes; (void)n_in; (void)out_size;

    cudaFuncSetAttribute(qnn_main_kernel,
                         cudaFuncAttributeMaxDynamicSharedMemorySize, SMEM_BYTES);

    build_W_kernel<<<1, 512>>>(weights, fc_w);
    qnn_main_kernel<<<304, BLK, SMEM_BYTES>>>(x, fc_b, out);
}

// round 13
// speedup vs baseline: 1.2887x; 1.2796x over previous
#include <cuda_runtime.h>

#define NQ 6
#define DIM 64
#define NL 8
#define BATCH 262144
#define NCLS 4

typedef unsigned long long u64;

// Precomputed circuit operator (transposed) and folded sign/fc matrix.
// g_Wt[j*64 + i] = W[i][j]  (complex, float2 = {re, im})
__device__ float2 g_Wt[DIM * DIM];
__device__ float4 g_G[DIM];   // G[i][k] = sum_q sign(i,q) * fc_w[k][q]

__device__ __forceinline__ float2 cmul(float2 a, float2 b) {
    return make_float2(a.x * b.x - a.y * b.y, a.x * b.y + a.y * b.x);
}

__device__ __forceinline__ u64 fma2(u64 a, u64 b, u64 c) {
    u64 d;
    asm("fma.rn.f32x2 %0, %1, %2, %3;" : "=l"(d) : "l"(a), "l"(b), "l"(c));
    return d;
}

// Pack {v, v} into a 64-bit register pair (ALU pipe, not LSU).
__device__ __forceinline__ u64 dup2(float v) {
    u64 d;
    asm("mov.b64 %0, {%1, %1};" : "=l"(d) : "f"(v));
    return d;
}

// ---------------------------------------------------------------------------
// Kernel 1: build the full 64x64 circuit unitary from weights (one block).
//   - all 48 gate matrices precomputed once (trig out of the sweeps)
//   - each layer's 6 CNOTs collapsed into ONE permutation sweep (ping-pong)
//   => 48 rot sweeps + 8 perm sweeps, all pure LDS/FFMA.
// ---------------------------------------------------------------------------
#define BW_SMEM (DIM * DIM * 8 * 2 + 48 * 4 * 8 + 64 * 4)

__global__ void build_W_kernel(const float* __restrict__ weights,
                               const float* __restrict__ fc_w) {
    extern __shared__ char bsm[];
    float2* bufA = (float2*)bsm;                         // 32 KB
    float2* bufB = bufA + DIM * DIM;                     // 32 KB
    float2* Umat = bufB + DIM * DIM;                     // 48 gates x 4 entries
    int*    perm = (int*)(Umat + 48 * 4);                // 64 ints

    const int tid = threadIdx.x;
    const int nthr = blockDim.x;

    // Phase 0: gate matrices (48 threads, one trig pass)
    if (tid < NL * NQ) {
        const float phi = weights[tid * 3 + 0];
        const float th  = weights[tid * 3 + 1];
        const float om  = weights[tid * 3 + 2];
        const float ch = cosf(0.5f * th), sh = sinf(0.5f * th);
        const float a  = 0.5f * (phi + om), d = 0.5f * (phi - om);
        const float ca = cosf(a), sa = sinf(a);
        const float cd = cosf(d), sd = sinf(d);
        Umat[tid * 4 + 0] = make_float2( ch * ca, -ch * sa);  // u00
        Umat[tid * 4 + 1] = make_float2(-sh * cd, -sh * sd);  // u01
        Umat[tid * 4 + 2] = make_float2( sh * cd, -sh * sd);  // u10
        Umat[tid * 4 + 3] = make_float2( ch * ca,  ch * sa);  // u11
    }

    // Init A = I
    for (int idx = tid; idx < DIM * DIM; idx += nthr) {
        int i = idx >> 6, j = idx & 63;
        bufA[idx] = make_float2(i == j ? 1.0f : 0.0f, 0.0f);
    }
    __syncthreads();

    float2* cur = bufA;
    float2* nxt = bufB;

    for (int l = 0; l < NL; l++) {
        // --- rotation sweeps (in place on cur) ---
        for (int q = 0; q < NQ; q++) {
            const int b = 5 - q;
            const int mask = 1 << b;
            const float2 u00 = Umat[(l * NQ + q) * 4 + 0];
            const float2 u01 = Umat[(l * NQ + q) * 4 + 1];
            const float2 u10 = Umat[(l * NQ + q) * 4 + 2];
            const float2 u11 = Umat[(l * NQ + q) * 4 + 3];

            for (int idx = tid; idx < 32 * DIM; idx += nthr) {
                const int j  = idx & 63;
                const int pr = idx >> 6;                       // 5-bit
                const int r0 = ((pr >> b) << (b + 1)) | (pr & (mask - 1));
                const int r1 = r0 | mask;
                const float2 A = cur[r0 * 64 + j];
                const float2 B = cur[r1 * 64 + j];
                float2 nA = cmul(u00, A);
                float2 nB = cmul(u10, A);
                float2 tA = cmul(u01, B);
                float2 tB = cmul(u11, B);
                cur[r0 * 64 + j] = make_float2(nA.x + tA.x, nA.y + tA.y);
                cur[r1 * 64 + j] = make_float2(nB.x + tB.x, nB.y + tB.y);
            }
            __syncthreads();
        }

        // --- full CNOT-ring permutation: sigma(x) = gates applied in order ---
        const int r = (l % (NQ - 1)) + 1;
        if (tid < DIM) {
            int y = tid;
            for (int q = 0; q < NQ; q++) {
                const int bc = 5 - q;
                const int bt = 5 - ((q + r) % NQ);
                y ^= ((y >> bc) & 1) << bt;
            }
            perm[tid] = y;     // B[sigma(x)] = A[x]
        }
        __syncthreads();
        for (int idx = tid; idx < DIM * DIM; idx += nthr) {
            const int x = idx >> 6, j = idx & 63;
            nxt[perm[x] * 64 + j] = cur[idx];
        }
        __syncthreads();
        float2* t = cur; cur = nxt; nxt = t;
    }

    // Write transposed operator: g_Wt[j*64+i] = M[i][j]
    for (int idx = tid; idx < DIM * DIM; idx += nthr) {
        const int j = idx >> 6, i = idx & 63;
        g_Wt[idx] = cur[i * 64 + j];
    }
    // Folded sign/fc matrix G
    for (int i = tid; i < DIM; i += nthr) {
        float4 g = make_float4(0.f, 0.f, 0.f, 0.f);
        for (int q = 0; q < NQ; q++) {
            const float sgn = ((i >> (5 - q)) & 1) ? -1.0f : 1.0f;
            g.x += sgn * fc_w[0 * NQ + q];
            g.y += sgn * fc_w[1 * NQ + q];
            g.z += sgn * fc_w[2 * NQ + q];
            g.w += sgn * fc_w[3 * NQ + q];
        }
        g_G[i] = g;
    }
}

// ---------------------------------------------------------------------------
// Kernel 2: batched complex matvec via packed fma.rn.f32x2.
// One warp handles 8 samples per chunk; lane t owns output rows 2t, 2t+1.
// x staged PLAIN in shared (one broadcast LDS.128 per j4 per sample);
// the packed {x,x} operand is built with mov.b64 on the ALU pipe.
// ---------------------------------------------------------------------------
#define BLK 256
#define WPB (BLK / 32)
#define SPW 8
#define STAGE_STRIDE 272                        // bytes/sample: 64 floats + pad
#define EPI_STRIDE 528                          // bytes/sample for epilogue
#define WARP_SCRATCH 4352                       // >= 8*528, 128B aligned
#define SMEM_BYTES (DIM * DIM * 8 + WPB * WARP_SCRATCH)   // 32768 + 34816

__global__ __launch_bounds__(BLK, 2) void qnn_main_kernel(
    const float* __restrict__ x,
    const float* __restrict__ fc_b,
    float* __restrict__ out) {
    extern __shared__ char smem[];
    // W region: [j][lane] as ulonglong2 = {{re0,im0},{re1,im1}} rows 2lane,2lane+1
    ulonglong2* WshQ = (ulonglong2*)smem;
    char* scratch_all = smem + DIM * DIM * 8;

    const int tid  = threadIdx.x;
    const int warp = tid >> 5;
    const int lane = tid & 31;

    {
        const ulonglong2* Wg = (const ulonglong2*)g_Wt;
#pragma unroll
        for (int idx = tid; idx < DIM * DIM / 2; idx += BLK) WshQ[idx] = Wg[idx];
    }
    __syncthreads();

    const float4 Ga = g_G[2 * lane];
    const float4 Gb = g_G[2 * lane + 1];

    char* scr = scratch_all + warp * WARP_SCRATCH;

    const int gwarp   = blockIdx.x * WPB + warp;
    const int nwarps  = gridDim.x * WPB;
    const int nchunks = BATCH / SPW;

    for (int chunk = gwarp; chunk < nchunks; chunk += nwarps) {
        const int b0 = chunk * SPW;

        // ---- load 8 samples, squared norms, stage plain into shared ----
        float n2[SPW];
        __syncwarp();
#pragma unroll
        for (int s = 0; s < SPW; s++) {
            float2 v = ((const float2*)(x + (size_t)(b0 + s) * DIM))[lane];
            float sq = fmaf(v.x, v.x, v.y * v.y);
#pragma unroll
            for (int off = 16; off > 0; off >>= 1)
                sq += __shfl_xor_sync(0xffffffffu, sq, off);
            n2[s] = sq;
            ((float2*)(scr + s * STAGE_STRIDE))[lane] = v;
        }
        __syncwarp();

        // ---- y = W x for 8 samples; packed complex accumulators ----
        u64 acc0[SPW], acc1[SPW];
#pragma unroll
        for (int s = 0; s < SPW; s++) { acc0[s] = 0ull; acc1[s] = 0ull; }

#pragma unroll 2
        for (int j4 = 0; j4 < DIM / 4; j4++) {
            const ulonglong2 wq0 = WshQ[(j4 * 4 + 0) * 32 + lane];
            const ulonglong2 wq1 = WshQ[(j4 * 4 + 1) * 32 + lane];
            const ulonglong2 wq2 = WshQ[(j4 * 4 + 2) * 32 + lane];
            const ulonglong2 wq3 = WshQ[(j4 * 4 + 3) * 32 + lane];
#pragma unroll
            for (int s = 0; s < SPW; s++) {
                const float4 xv =
                    *(const float4*)(scr + s * STAGE_STRIDE + j4 * 16);
                const u64 x0 = dup2(xv.x);
                const u64 x1 = dup2(xv.y);
                const u64 x2 = dup2(xv.z);
                const u64 x3 = dup2(xv.w);
                acc0[s] = fma2(wq0.x, x0, acc0[s]);
                acc1[s] = fma2(wq0.y, x0, acc1[s]);
                acc0[s] = fma2(wq1.x, x1, acc0[s]);
                acc1[s] = fma2(wq1.y, x1, acc1[s]);
                acc0[s] = fma2(wq2.x, x2, acc0[s]);
                acc1[s] = fma2(wq2.y, x2, acc1[s]);
                acc0[s] = fma2(wq3.x, x3, acc0[s]);
                acc1[s] = fma2(wq3.y, x3, acc1[s]);
            }
        }

        // ---- epilogue: probs -> folded head -> shared transpose reduce ----
        __syncwarp();
#pragma unroll
        for (int s = 0; s < SPW; s++) {
            const float inv = 1.0f / fmaxf(n2[s], 1e-24f);
            float r0, i0, r1, i1;
            asm("mov.b64 {%0, %1}, %2;" : "=f"(r0), "=f"(i0) : "l"(acc0[s]));
            asm("mov.b64 {%0, %1}, %2;" : "=f"(r1), "=f"(i1) : "l"(acc1[s]));
            const float p0 = fmaf(r0, r0, i0 * i0) * inv;
            const float p1 = fmaf(r1, r1, i1 * i1) * inv;
            float4 part;
            part.x = fmaf(p0, Ga.x, p1 * Gb.x);
            part.y = fmaf(p0, Ga.y, p1 * Gb.y);
            part.z = fmaf(p0, Ga.z, p1 * Gb.z);
            part.w = fmaf(p0, Ga.w, p1 * Gb.w);
            ((float4*)(scr + s * EPI_STRIDE))[lane] = part;
        }
        __syncwarp();

        // lane -> (sample = lane>>2, class = lane&3); sum 32 partials.
        {
            const int s = lane >> 2;
            const int c = lane & 3;
            const float* base = (const float*)(scr + s * EPI_STRIDE) + c;
            float a0 = 0.f, a1 = 0.f, a2 = 0.f, a3 = 0.f;
#pragma unroll
            for (int l = 0; l < 32; l += 4) {
                a0 += base[(l + 0) * 4];
                a1 += base[(l + 1) * 4];
                a2 += base[(l + 2) * 4];
                a3 += base[(l + 3) * 4];
            }
            const float res = (a0 + a1) + (a2 + a3) + fc_b[c];
            out[(size_t)b0 * NCLS + lane] = res;   // fully coalesced 128B
        }
        __syncwarp();
    }
}

// ---------------------------------------------------------------------------
// Launch
// ---------------------------------------------------------------------------
extern "C" void kernel_launch(void* const* d_in, const int* in_sizes, int n_in,
                              void* d_out, int out_size) {
    const float* x       = (const float*)d_in[0];   // [262144, 64]
    const float* weights = (const float*)d_in[1];   // [8, 6, 3]
    const float* fc_w    = (const float*)d_in[2];   // [4, 6]
    const float* fc_b    = (const float*)d_in[3];   // [4]
    float* out           = (float*)d_out;           // [262144, 4]

    (void)in_sizes; (void)n_in; (void)out_size;

    static int attr_done = 0;
    if (!attr_done) {
        cudaFuncSetAttribute(qnn_main_kernel,
                             cudaFuncAttributeMaxDynamicSharedMemorySize,
                             SMEM_BYTES);
        cudaFuncSetAttribute(build_W_kernel,
                             cudaFuncAttributeMaxDynamicSharedMemorySize,
                             BW_SMEM);
        attr_done = 1;
    }

    build_W_kernel<<<1, 512, BW_SMEM>>>(weights, fc_w);
    qnn_main_kernel<<<304, BLK, SMEM_BYTES>>>(x, fc_b, out);
}